// round 12
// baseline (speedup 1.0000x reference)
#include <cuda_runtime.h>

#define PI2 6.28318530717958647692f

typedef unsigned long long u64;

__device__ __forceinline__ u64 pk2(float lo, float hi) {
    u64 r; asm("mov.b64 %0,{%1,%2};" : "=l"(r) : "f"(lo), "f"(hi)); return r;
}
__device__ __forceinline__ void fma2(u64 &d, u64 a, u64 b) {
    asm("fma.rn.f32x2 %0,%1,%2,%0;" : "+l"(d) : "l"(a), "l"(b));
}
__device__ __forceinline__ float2 upk(u64 v) {
    float2 f; asm("mov.b64 {%0,%1},%2;" : "=f"(f.x), "=f"(f.y) : "l"(v)); return f;
}
__device__ __forceinline__ u64 add2(u64 a, u64 b) {
    u64 r; asm("add.rn.f32x2 %0,%1,%2;" : "=l"(r) : "l"(a), "l"(b)); return r;
}
__device__ __forceinline__ u64 sub2(u64 a, u64 b) {
    return add2(a, b ^ 0x8000000080000000ULL);
}

// Scratch (device globals — no allocation allowed).
static __device__ float2 g_xft[512 * 1024];   // [mode][b*32+i]
static __device__ float2 g_wt [512 * 1024];   // [mode][i*32+o]
static __device__ float2 g_oft[1024 * 512];   // [b*32+o][mode]

// ---------------------------------------------------------------------------
// K0: tiled transpose of weights [io][mk] -> [mk][io]
// ---------------------------------------------------------------------------
__global__ void __launch_bounds__(256) k0_wt(const float* __restrict__ wr,
                                             const float* __restrict__ wi) {
    __shared__ float2 tile[32][33];
    int bm  = blockIdx.x & 15;
    int bio = blockIdx.x >> 4;
    int mk0 = bm * 32, io0 = bio * 32;
    int c  = threadIdx.x & 31;
    int r4 = threadIdx.x >> 5;
    #pragma unroll
    for (int k = 0; k < 4; k++) {
        int r = r4 + 8 * k;
        size_t src = (size_t)(io0 + r) * 512 + mk0 + c;
        tile[r][c] = make_float2(wr[src], wi[src]);
    }
    __syncthreads();
    #pragma unroll
    for (int k = 0; k < 4; k++) {
        int c2 = r4 + 8 * k;
        g_wt[(size_t)(mk0 + c2) * 1024 + io0 + c] = tile[c][c2];
    }
}

// ---------------------------------------------------------------------------
// K1: forward truncated DFT with radix-4 folding. One block per (b,i).
// ---------------------------------------------------------------------------
__global__ void __launch_bounds__(256, 3) k1_forward(const float* __restrict__ x) {
    // stage-1 tables [w<32][16 ky slots, perm = 0,4,8,12,1,5,9,13,2,6,10,14,3,7,11,15]
    __shared__ __align__(16) float t1c[512];   // cos(2pi ky w/128)
    __shared__ __align__(16) float t1s[512];   // -sin
    __shared__ u64 TgF[128];                   // pk(cos, -sin)   (forward)
    __shared__ u64 TgG[128];                   // pk(sin,  cos)
    __shared__ float2 ys[128 * 17];            // y[h][ky], stride 17

    int t  = threadIdx.x;
    int bi = blockIdx.x;

    for (int idx = t; idx < 512; idx += 256) {
        int w = idx >> 4, slot = idx & 15;
        int ky = (slot >> 2) + (slot & 3) * 4;
        float s, c;
        sincosf(PI2 * (float)((ky * w) & 127) * (1.0f / 128.0f), &s, &c);
        t1c[idx] = c;
        t1s[idx] = -s;
    }
    for (int p = t; p < 128; p += 256) {
        float s, c;
        sincosf(PI2 * (float)p * (1.0f / 128.0f), &s, &c);
        TgF[p] = pk2(c, -s);
        TgG[p] = pk2(s, c);
    }
    __syncthreads();

    // ---- stage 1: thread = (h = t>>1, half = t&1); radix-4 over w ----
    {
        int h = t >> 1, half = t & 1;
        const float4* xr4 = (const float4*)(x + ((size_t)bi * 128 + h) * 128);
        u64 yre[2] = {0,0}, yie[2] = {0,0};    // even kys: 2half + {0,4,8,12}
        u64 yro[2] = {0,0}, yio[2] = {0,0};    // odd  kys: 2half + {1,5,9,13}
        #pragma unroll
        for (int w4 = 0; w4 < 8; w4++) {
            float4 X0 = xr4[w4], X1 = xr4[w4 + 8], X2 = xr4[w4 + 16], X3 = xr4[w4 + 24];
            float x0a[4] = {X0.x, X0.y, X0.z, X0.w};
            float x1a[4] = {X1.x, X1.y, X1.z, X1.w};
            float x2a[4] = {X2.x, X2.y, X2.z, X2.w};
            float x3a[4] = {X3.x, X3.y, X3.z, X3.w};
            #pragma unroll
            for (int d = 0; d < 4; d++) {
                int w = w4 * 4 + d;
                float p  = x0a[d] + x2a[d];
                float q  = x1a[d] + x3a[d];
                float tt = half ? (p - q) : (p + q);
                float r  = x0a[d] - x2a[d];
                float s  = x1a[d] - x3a[d];
                float sn = -s;
                float ui = half ? s : sn;      // odd ky: u = r + i*ui
                float un = half ? sn : s;      // -ui
                const float* cb = t1c + w * 16 + half * 8;
                const float* sb = t1s + w * 16 + half * 8;
                ulonglong2 ce = *(const ulonglong2*)cb;
                ulonglong2 co = *(const ulonglong2*)(cb + 4);
                ulonglong2 se = *(const ulonglong2*)sb;
                ulonglong2 so = *(const ulonglong2*)(sb + 4);
                u64 td = pk2(tt, tt);
                fma2(yre[0], td, ce.x); fma2(yre[1], td, ce.y);
                fma2(yie[0], td, se.x); fma2(yie[1], td, se.y);
                u64 urd = pk2(r, r);
                u64 uid = pk2(ui, ui);
                u64 und = pk2(un, un);
                // y += u * (C + iS'):  re += ur*C - ui*S'; im += ur*S' + ui*C
                fma2(yro[0], urd, co.x); fma2(yro[1], urd, co.y);
                fma2(yro[0], und, so.x); fma2(yro[1], und, so.y);
                fma2(yio[0], urd, so.x); fma2(yio[1], urd, so.y);
                fma2(yio[0], uid, co.x); fma2(yio[1], uid, co.y);
            }
        }
        #pragma unroll
        for (int g = 0; g < 2; g++) {
            float2 er = upk(yre[g]), ei = upk(yie[g]);
            float2 orr = upk(yro[g]), oi = upk(yio[g]);
            int base = h * 17 + 2 * half + 8 * g;
            ys[base]     = make_float2(er.x, ei.x);   // ky = 2half+8g
            ys[base + 4] = make_float2(er.y, ei.y);   // ky = 2half+8g+4
            ys[base + 1] = make_float2(orr.x, oi.x);  // ky = 2half+8g+1
            ys[base + 5] = make_float2(orr.y, oi.y);  // ky = 2half+8g+5
        }
    }
    __syncthreads();

    // ---- stage 2: thread = (ky = t&15, m-pair p = t>>4), radix-4 over h ----
    {
        int ky = t & 15, p = t >> 4;
        int q  = p >> 1;                 // class = q & 3 (warp-uniform)
        int c  = q & 3;
        int m0 = (q & 3) + ((q >= 4) ? 16 : 0) + (p & 1) * 8;
        int m1 = m0 + 4;
        int kx0 = (m0 < 16) ? m0 : 96 + m0;
        int kx1 = kx0 + 4;
        u64 acc0 = 0, acc1 = 0;
        int i0 = 0, i1 = 0;
        #pragma unroll 4
        for (int h = 0; h < 32; h++) {
            float2 y0 = ys[h * 17 + ky];
            float2 y1 = ys[(h + 32) * 17 + ky];
            float2 y2 = ys[(h + 64) * 17 + ky];
            float2 y3 = ys[(h + 96) * 17 + ky];
            float ur, ui;
            if (c == 0)      { ur = (y0.x + y2.x) + (y1.x + y3.x); ui = (y0.y + y2.y) + (y1.y + y3.y); }
            else if (c == 2) { ur = (y0.x + y2.x) - (y1.x + y3.x); ui = (y0.y + y2.y) - (y1.y + y3.y); }
            else if (c == 1) { ur = (y0.x - y2.x) + (y1.y - y3.y); ui = (y0.y - y2.y) - (y1.x - y3.x); }
            else             { ur = (y0.x - y2.x) - (y1.y - y3.y); ui = (y0.y - y2.y) + (y1.x - y3.x); }
            u64 urd = pk2(ur, ur), uid = pk2(ui, ui);
            fma2(acc0, urd, TgF[i0]); fma2(acc0, uid, TgG[i0]);
            fma2(acc1, urd, TgF[i1]); fma2(acc1, uid, TgG[i1]);
            i0 = (i0 + kx0) & 127; i1 = (i1 + kx1) & 127;
        }
        float2 a0 = upk(acc0), a1 = upk(acc1);
        g_xft[(size_t)(m0 * 16 + ky) * 1024 + bi] =
            make_float2(a0.x * 0.0078125f, a0.y * 0.0078125f);
        g_xft[(size_t)(m1 * 16 + ky) * 1024 + bi] =
            make_float2(a1.x * 0.0078125f, a1.y * 0.0078125f);
    }
}

// ---------------------------------------------------------------------------
// K2: per-mode channel mixing. One block per mode, 256 threads, 4-wide o tile.
// ---------------------------------------------------------------------------
__global__ void __launch_bounds__(256) k2_mix() {
    __shared__ float2 xfS[1024];
    __shared__ __align__(16) float2 wS[1024];
    int t  = threadIdx.x;
    int mk = blockIdx.x;
    for (int j = t; j < 1024; j += 256) {
        xfS[j] = g_xft[(size_t)mk * 1024 + j];
        wS[j]  = g_wt [(size_t)mk * 1024 + j];
    }
    __syncthreads();
    int b  = t >> 3;
    int o0 = (t & 7) * 4;
    float ar[4] = {}, ai[4] = {};
    #pragma unroll 8
    for (int i = 0; i < 32; i++) {
        float2 xv = xfS[b * 32 + i];
        const float4* wp = (const float4*)(wS + i * 32 + o0);
        float4 wa = wp[0], wb = wp[1];
        ar[0] = fmaf(xv.x, wa.x, ar[0]); ar[0] = fmaf(-xv.y, wa.y, ar[0]);
        ai[0] = fmaf(xv.x, wa.y, ai[0]); ai[0] = fmaf( xv.y, wa.x, ai[0]);
        ar[1] = fmaf(xv.x, wa.z, ar[1]); ar[1] = fmaf(-xv.y, wa.w, ar[1]);
        ai[1] = fmaf(xv.x, wa.w, ai[1]); ai[1] = fmaf( xv.y, wa.z, ai[1]);
        ar[2] = fmaf(xv.x, wb.x, ar[2]); ar[2] = fmaf(-xv.y, wb.y, ar[2]);
        ai[2] = fmaf(xv.x, wb.y, ai[2]); ai[2] = fmaf( xv.y, wb.x, ai[2]);
        ar[3] = fmaf(xv.x, wb.z, ar[3]); ar[3] = fmaf(-xv.y, wb.w, ar[3]);
        ai[3] = fmaf(xv.x, wb.w, ai[3]); ai[3] = fmaf( xv.y, wb.z, ai[3]);
    }
    size_t base = (size_t)(b * 32 + o0) * 512 + mk;
    #pragma unroll
    for (int k = 0; k < 4; k++)
        g_oft[base + (size_t)k * 512] = make_float2(ar[k], ai[k]);
}

// ---------------------------------------------------------------------------
// K3: inverse with radix-4 folding in both stages. One block per (b,o).
// ---------------------------------------------------------------------------
__global__ void __launch_bounds__(256, 3) k3_inverse(float* __restrict__ out) {
    __shared__ float2 ofS[512];
    __shared__ u64 TgP[128];                  // pk(cos,  sin)
    __shared__ u64 TgQ[128];                  // pk(-sin, cos)
    __shared__ __align__(16) float twc [512]; // [ky][w<32] cos
    __shared__ __align__(16) float tws [512]; // sin
    __shared__ __align__(16) float twsn[512]; // -sin
    __shared__ float2 As[128 * 17];           // stride-17 pad

    int t  = threadIdx.x;
    int bo = blockIdx.x;

    for (int p = t; p < 128; p += 256) {
        float s, c;
        sincosf(PI2 * (float)p * (1.0f / 128.0f), &s, &c);
        TgP[p] = pk2(c, s);
        TgQ[p] = pk2(-s, c);
    }
    for (int idx = t; idx < 512; idx += 256) {
        ofS[idx] = g_oft[(size_t)bo * 512 + idx];
        int ky = idx >> 5, w = idx & 31;
        float s, c;
        sincosf(PI2 * (float)((ky * w) & 127) * (1.0f / 128.0f), &s, &c);
        twc[idx]  = c;
        tws[idx]  = s;
        twsn[idx] = -s;
    }
    __syncthreads();

    // ---- stage A: class sums over h<32, butterfly to 128 h ----
    {
        int ky = t & 15, hq = t >> 4;        // h in {hq, hq+16}
        u64 S[4][2] = {};
        #pragma unroll
        for (int m = 0; m < 32; m++) {
            const int kx = (m < 16) ? m : 96 + m;
            const int cc = m & 3;
            float2 ov = ofS[m * 16 + ky];
            u64 dor = pk2(ov.x, ov.x), doi = pk2(ov.y, ov.y);
            int i0 = (kx * hq) & 127;
            int i1 = (i0 + 16 * kx) & 127;
            fma2(S[cc][0], dor, TgP[i0]); fma2(S[cc][0], doi, TgQ[i0]);
            fma2(S[cc][1], dor, TgP[i1]); fma2(S[cc][1], doi, TgQ[i1]);
        }
        float sc = (ky == 0) ? 0.0078125f : 0.015625f;
        #pragma unroll
        for (int e = 0; e < 2; e++) {
            int h = hq + 16 * e;
            float2 s0 = upk(S[0][e]), s1 = upk(S[1][e]);
            float2 s2 = upk(S[2][e]), s3 = upk(S[3][e]);
            float Er = s0.x + s2.x, Ei = s0.y + s2.y;
            float Fr = s0.x - s2.x, Fi = s0.y - s2.y;
            float Gr = s1.x + s3.x, Gi = s1.y + s3.y;
            float Hr = s1.x - s3.x, Hi = s1.y - s3.y;
            As[h * 17 + ky]        = make_float2((Er + Gr) * sc, (Ei + Gi) * sc);
            As[(h + 32) * 17 + ky] = make_float2((Fr - Hi) * sc, (Fi + Hr) * sc);
            As[(h + 64) * 17 + ky] = make_float2((Er - Gr) * sc, (Ei - Gi) * sc);
            As[(h + 96) * 17 + ky] = make_float2((Fr + Hi) * sc, (Fi - Hr) * sc);
        }
    }
    __syncthreads();

    // ---- stage B: thread = (wq = (t&7)*4, hg = t>>3), 2 passes of 2 h ----
    {
        float* orow = out + (size_t)bo * 16384;
        int wq = (t & 7) * 4;
        int hg = t >> 3;
        #pragma unroll
        for (int pass = 0; pass < 2; pass++) {
            int h0 = hg * 4 + pass * 2;
            u64 R0[2][2] = {}, R2[2][2] = {};
            u64 F1r[2][2] = {}, F1i[2][2] = {}, F3r[2][2] = {}, F3i[2][2] = {};
            #pragma unroll
            for (int ky = 0; ky < 16; ky++) {
                const int cc = ky & 3;
                ulonglong2 c2  = *(const ulonglong2*)(twc  + ky * 32 + wq);
                ulonglong2 sn2 = *(const ulonglong2*)(twsn + ky * 32 + wq);
                ulonglong2 s2v = (cc & 1) ? *(const ulonglong2*)(tws + ky * 32 + wq)
                                          : c2;
                #pragma unroll
                for (int dh = 0; dh < 2; dh++) {
                    float2 a = As[(h0 + dh) * 17 + ky];
                    u64 dar = pk2(a.x, a.x), dai = pk2(a.y, a.y);
                    if (cc == 0) {
                        fma2(R0[dh][0], dar, c2.x);  fma2(R0[dh][1], dar, c2.y);
                        fma2(R0[dh][0], dai, sn2.x); fma2(R0[dh][1], dai, sn2.y);
                    } else if (cc == 2) {
                        fma2(R2[dh][0], dar, c2.x);  fma2(R2[dh][1], dar, c2.y);
                        fma2(R2[dh][0], dai, sn2.x); fma2(R2[dh][1], dai, sn2.y);
                    } else if (cc == 1) {
                        fma2(F1r[dh][0], dar, c2.x);  fma2(F1r[dh][1], dar, c2.y);
                        fma2(F1r[dh][0], dai, sn2.x); fma2(F1r[dh][1], dai, sn2.y);
                        fma2(F1i[dh][0], dar, s2v.x); fma2(F1i[dh][1], dar, s2v.y);
                        fma2(F1i[dh][0], dai, c2.x);  fma2(F1i[dh][1], dai, c2.y);
                    } else {
                        fma2(F3r[dh][0], dar, c2.x);  fma2(F3r[dh][1], dar, c2.y);
                        fma2(F3r[dh][0], dai, sn2.x); fma2(F3r[dh][1], dai, sn2.y);
                        fma2(F3i[dh][0], dar, s2v.x); fma2(F3i[dh][1], dar, s2v.y);
                        fma2(F3i[dh][0], dai, c2.x);  fma2(F3i[dh][1], dai, c2.y);
                    }
                }
            }
            #pragma unroll
            for (int dh = 0; dh < 2; dh++) {
                int h = h0 + dh;
                u64 o0[2], o1[2], o2[2], o3[2];
                #pragma unroll
                for (int wp = 0; wp < 2; wp++) {
                    u64 e  = add2(R0[dh][wp], R2[dh][wp]);
                    u64 f  = sub2(R0[dh][wp], R2[dh][wp]);
                    u64 g  = add2(F1r[dh][wp], F3r[dh][wp]);
                    u64 hh = sub2(F3i[dh][wp], F1i[dh][wp]);
                    o0[wp] = add2(e, g);  o2[wp] = sub2(e, g);
                    o1[wp] = add2(f, hh); o3[wp] = sub2(f, hh);
                }
                float2 a, b;
                a = upk(o0[0]); b = upk(o0[1]);
                *(float4*)(orow + (size_t)h * 128 + wq)      = make_float4(a.x, a.y, b.x, b.y);
                a = upk(o1[0]); b = upk(o1[1]);
                *(float4*)(orow + (size_t)h * 128 + wq + 32) = make_float4(a.x, a.y, b.x, b.y);
                a = upk(o2[0]); b = upk(o2[1]);
                *(float4*)(orow + (size_t)h * 128 + wq + 64) = make_float4(a.x, a.y, b.x, b.y);
                a = upk(o3[0]); b = upk(o3[1]);
                *(float4*)(orow + (size_t)h * 128 + wq + 96) = make_float4(a.x, a.y, b.x, b.y);
            }
        }
    }
}

// ---------------------------------------------------------------------------
extern "C" void kernel_launch(void* const* d_in, const int* in_sizes, int n_in,
                              void* d_out, int out_size) {
    const float* x  = (const float*)d_in[0];
    const float* wr = (const float*)d_in[1];
    const float* wi = (const float*)d_in[2];
    float* out = (float*)d_out;

    k0_wt<<<512, 256>>>(wr, wi);
    k1_forward<<<1024, 256>>>(x);
    k2_mix<<<512, 256>>>();
    k3_inverse<<<1024, 256>>>(out);
}

// round 13
// speedup vs baseline: 1.0111x; 1.0111x over previous
#include <cuda_runtime.h>

#define PI2 6.28318530717958647692f

typedef unsigned long long u64;

__device__ __forceinline__ u64 pk2(float lo, float hi) {
    u64 r; asm("mov.b64 %0,{%1,%2};" : "=l"(r) : "f"(lo), "f"(hi)); return r;
}
__device__ __forceinline__ void fma2(u64 &d, u64 a, u64 b) {
    asm("fma.rn.f32x2 %0,%1,%2,%0;" : "+l"(d) : "l"(a), "l"(b));
}
__device__ __forceinline__ float2 upk(u64 v) {
    float2 f; asm("mov.b64 {%0,%1},%2;" : "=f"(f.x), "=f"(f.y) : "l"(v)); return f;
}
__device__ __forceinline__ u64 add2(u64 a, u64 b) {
    u64 r; asm("add.rn.f32x2 %0,%1,%2;" : "=l"(r) : "l"(a), "l"(b)); return r;
}
__device__ __forceinline__ u64 sub2(u64 a, u64 b) {
    return add2(a, b ^ 0x8000000080000000ULL);
}

// Scratch (device globals — no allocation allowed).
static __device__ float2 g_xft[512 * 1024];   // [mode][b*32+i]
static __device__ float2 g_wt [512 * 1024];   // [mode][i*32+o]
static __device__ float2 g_oft[1024 * 512];   // [b*32+o][mode]

// ---------------------------------------------------------------------------
// K0: tiled transpose of weights [io][mk] -> [mk][io]
// ---------------------------------------------------------------------------
__global__ void __launch_bounds__(256) k0_wt(const float* __restrict__ wr,
                                             const float* __restrict__ wi) {
    __shared__ float2 tile[32][33];
    int bm  = blockIdx.x & 15;
    int bio = blockIdx.x >> 4;
    int mk0 = bm * 32, io0 = bio * 32;
    int c  = threadIdx.x & 31;
    int r4 = threadIdx.x >> 5;
    #pragma unroll
    for (int k = 0; k < 4; k++) {
        int r = r4 + 8 * k;
        size_t src = (size_t)(io0 + r) * 512 + mk0 + c;
        tile[r][c] = make_float2(wr[src], wi[src]);
    }
    __syncthreads();
    #pragma unroll
    for (int k = 0; k < 4; k++) {
        int c2 = r4 + 8 * k;
        g_wt[(size_t)(mk0 + c2) * 1024 + io0 + c] = tile[c][c2];
    }
}

// ---------------------------------------------------------------------------
// K1: forward truncated DFT with radix-4 folding. One block per (b,i).
// ---------------------------------------------------------------------------
__global__ void __launch_bounds__(256, 3) k1_forward(const float* __restrict__ x) {
    // stage-1 tables [w<32][16 ky slots, perm = 0,4,8,12,1,5,9,13,2,6,10,14,3,7,11,15]
    __shared__ __align__(16) float t1c[512];   // cos(2pi ky w/128)
    __shared__ __align__(16) float t1s[512];   // -sin
    __shared__ u64 TgF[128];                   // pk(cos, -sin)   (forward)
    __shared__ u64 TgG[128];                   // pk(sin,  cos)
    __shared__ float2 ys[128 * 17];            // y[h][ky], stride 17

    int t  = threadIdx.x;
    int bi = blockIdx.x;

    for (int idx = t; idx < 512; idx += 256) {
        int w = idx >> 4, slot = idx & 15;
        int ky = (slot >> 2) + (slot & 3) * 4;
        float s, c;
        sincosf(PI2 * (float)((ky * w) & 127) * (1.0f / 128.0f), &s, &c);
        t1c[idx] = c;
        t1s[idx] = -s;
    }
    for (int p = t; p < 128; p += 256) {
        float s, c;
        sincosf(PI2 * (float)p * (1.0f / 128.0f), &s, &c);
        TgF[p] = pk2(c, -s);
        TgG[p] = pk2(s, c);
    }
    __syncthreads();

    // ---- stage 1: thread = (h = t>>1, half = t&1); radix-4 over w ----
    {
        int h = t >> 1, half = t & 1;
        const float4* xr4 = (const float4*)(x + ((size_t)bi * 128 + h) * 128);
        u64 yre[2] = {0,0}, yie[2] = {0,0};    // even kys: 2half + {0,4,8,12}
        u64 yro[2] = {0,0}, yio[2] = {0,0};    // odd  kys: 2half + {1,5,9,13}
        #pragma unroll
        for (int w4 = 0; w4 < 8; w4++) {
            float4 X0 = xr4[w4], X1 = xr4[w4 + 8], X2 = xr4[w4 + 16], X3 = xr4[w4 + 24];
            float x0a[4] = {X0.x, X0.y, X0.z, X0.w};
            float x1a[4] = {X1.x, X1.y, X1.z, X1.w};
            float x2a[4] = {X2.x, X2.y, X2.z, X2.w};
            float x3a[4] = {X3.x, X3.y, X3.z, X3.w};
            #pragma unroll
            for (int d = 0; d < 4; d++) {
                int w = w4 * 4 + d;
                float p  = x0a[d] + x2a[d];
                float q  = x1a[d] + x3a[d];
                float tt = half ? (p - q) : (p + q);
                float r  = x0a[d] - x2a[d];
                float s  = x1a[d] - x3a[d];
                float sn = -s;
                float ui = half ? s : sn;      // odd ky: u = r + i*ui
                float un = half ? sn : s;      // -ui
                const float* cb = t1c + w * 16 + half * 8;
                const float* sb = t1s + w * 16 + half * 8;
                ulonglong2 ce = *(const ulonglong2*)cb;
                ulonglong2 co = *(const ulonglong2*)(cb + 4);
                ulonglong2 se = *(const ulonglong2*)sb;
                ulonglong2 so = *(const ulonglong2*)(sb + 4);
                u64 td = pk2(tt, tt);
                fma2(yre[0], td, ce.x); fma2(yre[1], td, ce.y);
                fma2(yie[0], td, se.x); fma2(yie[1], td, se.y);
                u64 urd = pk2(r, r);
                u64 uid = pk2(ui, ui);
                u64 und = pk2(un, un);
                // y += u * (C + iS'):  re += ur*C - ui*S'; im += ur*S' + ui*C
                fma2(yro[0], urd, co.x); fma2(yro[1], urd, co.y);
                fma2(yro[0], und, so.x); fma2(yro[1], und, so.y);
                fma2(yio[0], urd, so.x); fma2(yio[1], urd, so.y);
                fma2(yio[0], uid, co.x); fma2(yio[1], uid, co.y);
            }
        }
        #pragma unroll
        for (int g = 0; g < 2; g++) {
            float2 er = upk(yre[g]), ei = upk(yie[g]);
            float2 orr = upk(yro[g]), oi = upk(yio[g]);
            int base = h * 17 + 2 * half + 8 * g;
            ys[base]     = make_float2(er.x, ei.x);   // ky = 2half+8g
            ys[base + 4] = make_float2(er.y, ei.y);   // ky = 2half+8g+4
            ys[base + 1] = make_float2(orr.x, oi.x);  // ky = 2half+8g+1
            ys[base + 5] = make_float2(orr.y, oi.y);  // ky = 2half+8g+5
        }
    }
    __syncthreads();

    // ---- stage 2: thread = (ky = t&15, m-pair p = t>>4), radix-4 over h ----
    {
        int ky = t & 15, p = t >> 4;
        int q  = p >> 1;                 // class = q & 3 (warp-uniform)
        int c  = q & 3;
        int m0 = (q & 3) + ((q >= 4) ? 16 : 0) + (p & 1) * 8;
        int m1 = m0 + 4;
        int kx0 = (m0 < 16) ? m0 : 96 + m0;
        int kx1 = kx0 + 4;
        u64 acc0 = 0, acc1 = 0;
        int i0 = 0, i1 = 0;
        #pragma unroll 4
        for (int h = 0; h < 32; h++) {
            float2 y0 = ys[h * 17 + ky];
            float2 y1 = ys[(h + 32) * 17 + ky];
            float2 y2 = ys[(h + 64) * 17 + ky];
            float2 y3 = ys[(h + 96) * 17 + ky];
            float ur, ui;
            if (c == 0)      { ur = (y0.x + y2.x) + (y1.x + y3.x); ui = (y0.y + y2.y) + (y1.y + y3.y); }
            else if (c == 2) { ur = (y0.x + y2.x) - (y1.x + y3.x); ui = (y0.y + y2.y) - (y1.y + y3.y); }
            else if (c == 1) { ur = (y0.x - y2.x) + (y1.y - y3.y); ui = (y0.y - y2.y) - (y1.x - y3.x); }
            else             { ur = (y0.x - y2.x) - (y1.y - y3.y); ui = (y0.y - y2.y) + (y1.x - y3.x); }
            u64 urd = pk2(ur, ur), uid = pk2(ui, ui);
            fma2(acc0, urd, TgF[i0]); fma2(acc0, uid, TgG[i0]);
            fma2(acc1, urd, TgF[i1]); fma2(acc1, uid, TgG[i1]);
            i0 = (i0 + kx0) & 127; i1 = (i1 + kx1) & 127;
        }
        float2 a0 = upk(acc0), a1 = upk(acc1);
        g_xft[(size_t)(m0 * 16 + ky) * 1024 + bi] =
            make_float2(a0.x * 0.0078125f, a0.y * 0.0078125f);
        g_xft[(size_t)(m1 * 16 + ky) * 1024 + bi] =
            make_float2(a1.x * 0.0078125f, a1.y * 0.0078125f);
    }
}

// ---------------------------------------------------------------------------
// K2: per-mode channel mixing. One block per mode, 256 threads, 4-wide o tile.
// ---------------------------------------------------------------------------
__global__ void __launch_bounds__(256) k2_mix() {
    __shared__ float2 xfS[1024];
    __shared__ __align__(16) float2 wS[1024];
    int t  = threadIdx.x;
    int mk = blockIdx.x;
    for (int j = t; j < 1024; j += 256) {
        xfS[j] = g_xft[(size_t)mk * 1024 + j];
        wS[j]  = g_wt [(size_t)mk * 1024 + j];
    }
    __syncthreads();
    int b  = t >> 3;
    int o0 = (t & 7) * 4;
    float ar[4] = {}, ai[4] = {};
    #pragma unroll 8
    for (int i = 0; i < 32; i++) {
        float2 xv = xfS[b * 32 + i];
        const float4* wp = (const float4*)(wS + i * 32 + o0);
        float4 wa = wp[0], wb = wp[1];
        ar[0] = fmaf(xv.x, wa.x, ar[0]); ar[0] = fmaf(-xv.y, wa.y, ar[0]);
        ai[0] = fmaf(xv.x, wa.y, ai[0]); ai[0] = fmaf( xv.y, wa.x, ai[0]);
        ar[1] = fmaf(xv.x, wa.z, ar[1]); ar[1] = fmaf(-xv.y, wa.w, ar[1]);
        ai[1] = fmaf(xv.x, wa.w, ai[1]); ai[1] = fmaf( xv.y, wa.z, ai[1]);
        ar[2] = fmaf(xv.x, wb.x, ar[2]); ar[2] = fmaf(-xv.y, wb.y, ar[2]);
        ai[2] = fmaf(xv.x, wb.y, ai[2]); ai[2] = fmaf( xv.y, wb.x, ai[2]);
        ar[3] = fmaf(xv.x, wb.z, ar[3]); ar[3] = fmaf(-xv.y, wb.w, ar[3]);
        ai[3] = fmaf(xv.x, wb.w, ai[3]); ai[3] = fmaf( xv.y, wb.z, ai[3]);
    }
    size_t base = (size_t)(b * 32 + o0) * 512 + mk;
    #pragma unroll
    for (int k = 0; k < 4; k++)
        g_oft[base + (size_t)k * 512] = make_float2(ar[k], ai[k]);
}

// ---------------------------------------------------------------------------
// K3: inverse with radix-4 folding in both stages. One block per (b,o).
// ---------------------------------------------------------------------------
__global__ void __launch_bounds__(256, 3) k3_inverse(float* __restrict__ out) {
    __shared__ float2 ofS[512];
    __shared__ u64 TgP[128];                  // pk(cos,  sin)
    __shared__ u64 TgQ[128];                  // pk(-sin, cos)
    __shared__ __align__(16) float twc [512]; // [ky][w<32] cos
    __shared__ __align__(16) float tws [512]; // sin
    __shared__ __align__(16) float twsn[512]; // -sin
    __shared__ float2 As[128 * 17];           // stride-17 pad

    int t  = threadIdx.x;
    int bo = blockIdx.x;

    for (int p = t; p < 128; p += 256) {
        float s, c;
        sincosf(PI2 * (float)p * (1.0f / 128.0f), &s, &c);
        TgP[p] = pk2(c, s);
        TgQ[p] = pk2(-s, c);
    }
    for (int idx = t; idx < 512; idx += 256) {
        ofS[idx] = g_oft[(size_t)bo * 512 + idx];
        int ky = idx >> 5, w = idx & 31;
        float s, c;
        sincosf(PI2 * (float)((ky * w) & 127) * (1.0f / 128.0f), &s, &c);
        twc[idx]  = c;
        tws[idx]  = s;
        twsn[idx] = -s;
    }
    __syncthreads();

    // ---- stage A: class sums over h<32, butterfly to 128 h ----
    {
        int ky = t & 15, hq = t >> 4;        // h in {hq, hq+16}
        u64 S[4][2] = {};
        #pragma unroll
        for (int m = 0; m < 32; m++) {
            const int kx = (m < 16) ? m : 96 + m;
            const int cc = m & 3;
            float2 ov = ofS[m * 16 + ky];
            u64 dor = pk2(ov.x, ov.x), doi = pk2(ov.y, ov.y);
            int i0 = (kx * hq) & 127;
            int i1 = (i0 + 16 * kx) & 127;
            fma2(S[cc][0], dor, TgP[i0]); fma2(S[cc][0], doi, TgQ[i0]);
            fma2(S[cc][1], dor, TgP[i1]); fma2(S[cc][1], doi, TgQ[i1]);
        }
        float sc = (ky == 0) ? 0.0078125f : 0.015625f;
        #pragma unroll
        for (int e = 0; e < 2; e++) {
            int h = hq + 16 * e;
            float2 s0 = upk(S[0][e]), s1 = upk(S[1][e]);
            float2 s2 = upk(S[2][e]), s3 = upk(S[3][e]);
            float Er = s0.x + s2.x, Ei = s0.y + s2.y;
            float Fr = s0.x - s2.x, Fi = s0.y - s2.y;
            float Gr = s1.x + s3.x, Gi = s1.y + s3.y;
            float Hr = s1.x - s3.x, Hi = s1.y - s3.y;
            As[h * 17 + ky]        = make_float2((Er + Gr) * sc, (Ei + Gi) * sc);
            As[(h + 32) * 17 + ky] = make_float2((Fr - Hi) * sc, (Fi + Hr) * sc);
            As[(h + 64) * 17 + ky] = make_float2((Er - Gr) * sc, (Ei - Gi) * sc);
            As[(h + 96) * 17 + ky] = make_float2((Fr + Hi) * sc, (Fi - Hr) * sc);
        }
    }
    __syncthreads();

    // ---- stage B: thread = (wq = (t&7)*4, hg = t>>3), 2 passes of 2 h ----
    {
        float* orow = out + (size_t)bo * 16384;
        int wq = (t & 7) * 4;
        int hg = t >> 3;
        #pragma unroll
        for (int pass = 0; pass < 2; pass++) {
            int h0 = hg * 4 + pass * 2;
            u64 R0[2][2] = {}, R2[2][2] = {};
            u64 F1r[2][2] = {}, F1i[2][2] = {}, F3r[2][2] = {}, F3i[2][2] = {};
            #pragma unroll
            for (int ky = 0; ky < 16; ky++) {
                const int cc = ky & 3;
                ulonglong2 c2  = *(const ulonglong2*)(twc  + ky * 32 + wq);
                ulonglong2 sn2 = *(const ulonglong2*)(twsn + ky * 32 + wq);
                ulonglong2 s2v = (cc & 1) ? *(const ulonglong2*)(tws + ky * 32 + wq)
                                          : c2;
                #pragma unroll
                for (int dh = 0; dh < 2; dh++) {
                    float2 a = As[(h0 + dh) * 17 + ky];
                    u64 dar = pk2(a.x, a.x), dai = pk2(a.y, a.y);
                    if (cc == 0) {
                        fma2(R0[dh][0], dar, c2.x);  fma2(R0[dh][1], dar, c2.y);
                        fma2(R0[dh][0], dai, sn2.x); fma2(R0[dh][1], dai, sn2.y);
                    } else if (cc == 2) {
                        fma2(R2[dh][0], dar, c2.x);  fma2(R2[dh][1], dar, c2.y);
                        fma2(R2[dh][0], dai, sn2.x); fma2(R2[dh][1], dai, sn2.y);
                    } else if (cc == 1) {
                        fma2(F1r[dh][0], dar, c2.x);  fma2(F1r[dh][1], dar, c2.y);
                        fma2(F1r[dh][0], dai, sn2.x); fma2(F1r[dh][1], dai, sn2.y);
                        fma2(F1i[dh][0], dar, s2v.x); fma2(F1i[dh][1], dar, s2v.y);
                        fma2(F1i[dh][0], dai, c2.x);  fma2(F1i[dh][1], dai, c2.y);
                    } else {
                        fma2(F3r[dh][0], dar, c2.x);  fma2(F3r[dh][1], dar, c2.y);
                        fma2(F3r[dh][0], dai, sn2.x); fma2(F3r[dh][1], dai, sn2.y);
                        fma2(F3i[dh][0], dar, s2v.x); fma2(F3i[dh][1], dar, s2v.y);
                        fma2(F3i[dh][0], dai, c2.x);  fma2(F3i[dh][1], dai, c2.y);
                    }
                }
            }
            #pragma unroll
            for (int dh = 0; dh < 2; dh++) {
                int h = h0 + dh;
                u64 o0[2], o1[2], o2[2], o3[2];
                #pragma unroll
                for (int wp = 0; wp < 2; wp++) {
                    u64 e  = add2(R0[dh][wp], R2[dh][wp]);
                    u64 f  = sub2(R0[dh][wp], R2[dh][wp]);
                    u64 g  = add2(F1r[dh][wp], F3r[dh][wp]);
                    u64 hh = sub2(F3i[dh][wp], F1i[dh][wp]);
                    o0[wp] = add2(e, g);  o2[wp] = sub2(e, g);
                    o1[wp] = add2(f, hh); o3[wp] = sub2(f, hh);
                }
                float2 a, b;
                a = upk(o0[0]); b = upk(o0[1]);
                *(float4*)(orow + (size_t)h * 128 + wq)      = make_float4(a.x, a.y, b.x, b.y);
                a = upk(o1[0]); b = upk(o1[1]);
                *(float4*)(orow + (size_t)h * 128 + wq + 32) = make_float4(a.x, a.y, b.x, b.y);
                a = upk(o2[0]); b = upk(o2[1]);
                *(float4*)(orow + (size_t)h * 128 + wq + 64) = make_float4(a.x, a.y, b.x, b.y);
                a = upk(o3[0]); b = upk(o3[1]);
                *(float4*)(orow + (size_t)h * 128 + wq + 96) = make_float4(a.x, a.y, b.x, b.y);
            }
        }
    }
}

// ---------------------------------------------------------------------------
extern "C" void kernel_launch(void* const* d_in, const int* in_sizes, int n_in,
                              void* d_out, int out_size) {
    const float* x  = (const float*)d_in[0];
    const float* wr = (const float*)d_in[1];
    const float* wi = (const float*)d_in[2];
    float* out = (float*)d_out;

    k0_wt<<<512, 256>>>(wr, wi);
    k1_forward<<<1024, 256>>>(x);
    k2_mix<<<512, 256>>>();
    k3_inverse<<<1024, 256>>>(out);
}